// round 9
// baseline (speedup 1.0000x reference)
#include <cuda_runtime.h>
#include <cuda_bf16.h>

// Problem constants
#define B_   2
#define T_   128
#define C_   527
#define DA_  1024
#define DW_  300
#define H_   1024
#define BT_  (B_ * T_)   // 256

typedef unsigned long long u64;

// ---------------- device scratch ----------------
__device__ float g_apart[4 * BT_ * H_];  // split-K-4 partials for fc_1
__device__ float g_w[C_ * H_];           // fc_2 output [527,1024]
__device__ float g_vpart[4 * H_];        // veff partials (4 o-chunks)
__device__ float g_score0[BT_ * C_];     // partial score (h first half)
__device__ float g_score1[BT_ * C_];     // partial score (h second half)
__device__ float g_coef[BT_ * C_];       // softmax over T

__device__ __forceinline__ float tanh_fast(float x) {
    float y;
    asm("tanh.approx.f32 %0, %1;" : "=f"(y) : "f"(x));
    return y;
}
__device__ __forceinline__ void fma2(u64& d, u64 a, u64 b) {
    asm("fma.rn.f32x2 %0, %1, %2, %0;" : "+l"(d) : "l"(a), "l"(b));
}
__device__ __forceinline__ u64 dup2(float a) {
    u64 r;
    asm("mov.b64 %0, {%1, %1};" : "=l"(r) : "f"(a));
    return r;
}
__device__ __forceinline__ float unpk_sum(u64 v) {
    float lo, hi;
    asm("mov.b64 {%0,%1}, %2;" : "=f"(lo), "=f"(hi) : "l"(v));
    return lo + hi;
}
// acc += tanh(a*w) * v, packed over an h-pair
__device__ __forceinline__ void tvstep(u64& acc, u64 a, u64 w, u64 v) {
    u64 x;
    asm("mul.rn.f32x2 %0, %1, %2;" : "=l"(x) : "l"(a), "l"(w));
    float xl, xh;
    asm("mov.b64 {%0,%1}, %2;" : "=f"(xl), "=f"(xh) : "l"(x));
    float tl = tanh_fast(xl), th = tanh_fast(xh);
    u64 t;
    asm("mov.b64 %0, {%1,%2};" : "=l"(t) : "f"(tl), "f"(th));
    asm("fma.rn.f32x2 %0, %1, %2, %0;" : "+l"(acc) : "l"(t), "l"(v));
}

// ---------------- GEMM 8x8 n-paired: C[M,N] = A[M,K] . B[N,K]^T ----------------
// 64x128 tile, 128 threads, 8m x 8n microtile, f32x2 paired over n.
// As: [16 k][64 m] scalar; Bs: [16 k][128 n] scalar. N must be a multiple of 128.
__device__ __forceinline__ void gemm_nt8(const float* __restrict__ A,
                                         const float* __restrict__ B,
                                         float* __restrict__ C,
                                         int M, int N, int K, int Kc,
                                         int bx, int by, int bz,
                                         int tid, float* As, float* Bs) {
    int m0 = bx * 64;
    int n0 = by * 128;
    int k0g = bz * Kc;
    int Kend = min(k0g + Kc, K);
    float* Cout = C + (size_t)bz * M * N;

    int ar = tid >> 1;             // A row 0..63
    int ako = (tid & 1) * 8;       // A k offset 0/8
    int gmA = min(m0 + ar, M - 1);
    const float* Ap = A + (size_t)gmA * K + ako;
    const float* Bp = B + (size_t)(n0 + tid) * K;   // B row = n0+tid, all 16 k

    int tx = tid & 15;             // n = n0 + tx*8
    int ty = tid >> 4;             // m = m0 + ty*8

    u64 acc[8][4];
#pragma unroll
    for (int i = 0; i < 8; i++)
#pragma unroll
        for (int j = 0; j < 4; j++) acc[i][j] = 0ull;

    float a8[8], b16[16];
    {
        int kk = k0g;
        if (kk + 16 <= Kend) {
            float4 t0 = *(const float4*)(Ap + kk);
            float4 t1 = *(const float4*)(Ap + kk + 4);
            a8[0]=t0.x; a8[1]=t0.y; a8[2]=t0.z; a8[3]=t0.w;
            a8[4]=t1.x; a8[5]=t1.y; a8[6]=t1.z; a8[7]=t1.w;
#pragma unroll
            for (int q = 0; q < 4; q++) {
                float4 t = *(const float4*)(Bp + kk + q * 4);
                b16[q*4+0]=t.x; b16[q*4+1]=t.y; b16[q*4+2]=t.z; b16[q*4+3]=t.w;
            }
        } else {
#pragma unroll
            for (int i = 0; i < 8; i++) a8[i] = (kk + ako + i < Kend) ? Ap[kk + i] : 0.f;
#pragma unroll
            for (int i = 0; i < 16; i++) b16[i] = (kk + i < Kend) ? Bp[kk + i] : 0.f;
        }
    }

    for (int k0 = k0g; k0 < Kend; k0 += 16) {
#pragma unroll
        for (int i = 0; i < 8; i++) As[(ako + i) * 64 + ar] = a8[i];
#pragma unroll
        for (int i = 0; i < 16; i++) Bs[i * 128 + tid] = b16[i];
        __syncthreads();

        float na8[8], nb16[16];
        int kn = k0 + 16;
        bool more = kn < Kend;
        if (more) {
            if (kn + 16 <= Kend) {
                float4 t0 = *(const float4*)(Ap + kn);
                float4 t1 = *(const float4*)(Ap + kn + 4);
                na8[0]=t0.x; na8[1]=t0.y; na8[2]=t0.z; na8[3]=t0.w;
                na8[4]=t1.x; na8[5]=t1.y; na8[6]=t1.z; na8[7]=t1.w;
#pragma unroll
                for (int q = 0; q < 4; q++) {
                    float4 t = *(const float4*)(Bp + kn + q * 4);
                    nb16[q*4+0]=t.x; nb16[q*4+1]=t.y; nb16[q*4+2]=t.z; nb16[q*4+3]=t.w;
                }
            } else {
#pragma unroll
                for (int i = 0; i < 8; i++) na8[i] = (kn + ako + i < Kend) ? Ap[kn + i] : 0.f;
#pragma unroll
                for (int i = 0; i < 16; i++) nb16[i] = (kn + i < Kend) ? Bp[kn + i] : 0.f;
            }
        }

#pragma unroll
        for (int k = 0; k < 16; k++) {
            float4 amA = *(const float4*)&As[k * 64 + ty * 8];
            float4 amB = *(const float4*)&As[k * 64 + ty * 8 + 4];
            ulonglong2 bn0 = *(const ulonglong2*)&Bs[k * 128 + tx * 8];
            ulonglong2 bn1 = *(const ulonglong2*)&Bs[k * 128 + tx * 8 + 4];
            float am[8] = {amA.x, amA.y, amA.z, amA.w, amB.x, amB.y, amB.z, amB.w};
#pragma unroll
            for (int i = 0; i < 8; i++) {
                u64 p = dup2(am[i]);
                fma2(acc[i][0], p, bn0.x);
                fma2(acc[i][1], p, bn0.y);
                fma2(acc[i][2], p, bn1.x);
                fma2(acc[i][3], p, bn1.y);
            }
        }
        __syncthreads();
        if (more) {
#pragma unroll
            for (int i = 0; i < 8; i++) a8[i] = na8[i];
#pragma unroll
            for (int i = 0; i < 16; i++) b16[i] = nb16[i];
        }
    }

#pragma unroll
    for (int i = 0; i < 8; i++) {
        int gm = m0 + ty * 8 + i;
        if (gm >= M) continue;
        ulonglong2 o0, o1;
        o0.x = acc[i][0]; o0.y = acc[i][1];
        o1.x = acc[i][2]; o1.y = acc[i][3];
        *(ulonglong2*)&Cout[(size_t)gm * N + n0 + tx * 8] = o0;
        *(ulonglong2*)&Cout[(size_t)gm * N + n0 + tx * 8 + 4] = o1;
    }
}

// ---------------- K1 fat kernel: fc_1 gemm + fc_2 gemm + veff prep ----------------
// blocks [0,128): fc_1 split-K-4; [128,200): fc_2; [200,328): veff partials.
__global__ void __launch_bounds__(128) fat_kernel(const float* __restrict__ audio,
                                                  const float* __restrict__ word,
                                                  const float* __restrict__ W1,
                                                  const float* __restrict__ W2,
                                                  const float* __restrict__ W3,
                                                  const float* __restrict__ Wa) {
    __shared__ __align__(16) float As[16 * 64];
    __shared__ __align__(16) float Bs[16 * 128];
    __shared__ float red[4][33];
    int ib = blockIdx.x;
    int tid = threadIdx.x;
    if (ib < 128) {
        // fc_1: a partials = audio @ W1^T, split-K 4 (Kc = 256); 4 m x 8 n tiles
        int r = ib & 31;
        gemm_nt8(audio, W1, (float*)&g_apart[0], BT_, H_, DA_, DA_ / 4,
                 r & 3, r >> 2, ib >> 5, tid, As, Bs);
    } else if (ib < 200) {
        int j = ib - 128;   // 0..71 -> (x 0..8, y 0..7)
        gemm_nt8(word, W2, (float*)&g_w[0], C_, H_, DW_, DW_,
                 j % 9, j / 9, 0, tid, As, Bs);
    } else {
        // veff partials: p = 0..127; hb = p&31 (32 h), ob = p>>5 (256 o rows)
        int p = ib - 200;
        int hb = p & 31, ob = p >> 5;
        int hl = tid & 31;
        int og = tid >> 5;          // 0..3
        int h = hb * 32 + hl;
        float acc = 0.f;
#pragma unroll 8
        for (int o = ob * 256 + og; o < ob * 256 + 256; o += 4)
            acc += Wa[o] * W3[(size_t)o * H_ + h];
        red[og][hl] = acc;
        __syncthreads();
        if (og == 0)
            g_vpart[ob * H_ + h] = red[0][hl] + red[1][hl] + red[2][hl] + red[3][hl];
    }
}

// ---------------- K4: partial score over one H half, f32x2 packed ----------------
// CTA tile 16 bt x 64 c, 256 threads, 2bt x 2c per thread. grid (16, 9, 2).
__global__ void __launch_bounds__(256, 2) score_kernel() {
    __shared__ __align__(16) float a_s[16][64];
    __shared__ __align__(16) float w_s[64][68];
    __shared__ __align__(16) float v_s[64];
    int tid  = threadIdx.x;
    int lane = tid & 31;
    int warp = tid >> 5;            // 0..7
    int bt0  = blockIdx.x * 16;
    int c0   = blockIdx.y * 64;
    int hb0  = blockIdx.z * (H_ / 2);
    float* out = blockIdx.z ? g_score1 : g_score0;
    u64 p00 = 0ull, p01 = 0ull, p10 = 0ull, p11 = 0ull;

    for (int h0 = hb0; h0 < hb0 + H_ / 2; h0 += 64) {
        // a tile with fused split-K-4 merge
        {
            int r = tid >> 4;              // 0..15
            int c4 = (tid & 15) * 4;       // 0..60
            size_t ai = (size_t)(bt0 + r) * H_ + h0 + c4;
            const size_t S = (size_t)BT_ * H_;
            float4 x = *(const float4*)&g_apart[ai];
            float4 y = *(const float4*)&g_apart[S + ai];
            float4 z = *(const float4*)&g_apart[2 * S + ai];
            float4 w = *(const float4*)&g_apart[3 * S + ai];
            x.x = (x.x + y.x) + (z.x + w.x);
            x.y = (x.y + y.y) + (z.y + w.y);
            x.z = (x.z + y.z) + (z.z + w.z);
            x.w = (x.w + y.w) + (z.w + w.w);
            *(float4*)&a_s[r][c4] = x;
        }
        // v tile: sum the 4 o-chunk partials
        if (tid < 64) {
            int h = h0 + tid;
            v_s[tid] = g_vpart[h] + g_vpart[H_ + h] + g_vpart[2 * H_ + h] + g_vpart[3 * H_ + h];
        }
        // w tile, c-major
        {
            int c = tid >> 2, q = tid & 3;
            int cg = c0 + c;
            bool ok = cg < C_;
            const float4* wrow = (const float4*)(g_w + (size_t)(ok ? cg : C_ - 1) * H_ + h0);
            float4 z = make_float4(0.f, 0.f, 0.f, 0.f);
#pragma unroll
            for (int i = 0; i < 4; i++)
                *(float4*)&w_s[c][q * 16 + i * 4] = ok ? wrow[q * 4 + i] : z;
        }
        __syncthreads();

#pragma unroll
        for (int hh = 0; hh < 16; hh++) {
            ulonglong2 av0 = *(const ulonglong2*)&a_s[warp][hh * 4];
            ulonglong2 av1 = *(const ulonglong2*)&a_s[warp + 8][hh * 4];
            ulonglong2 wA  = *(const ulonglong2*)&w_s[lane][hh * 4];
            ulonglong2 wB  = *(const ulonglong2*)&w_s[lane + 32][hh * 4];
            ulonglong2 vv  = *(const ulonglong2*)&v_s[hh * 4];
            tvstep(p00, av0.x, wA.x, vv.x);
            tvstep(p01, av0.x, wB.x, vv.x);
            tvstep(p10, av1.x, wA.x, vv.x);
            tvstep(p11, av1.x, wB.x, vv.x);
            tvstep(p00, av0.y, wA.y, vv.y);
            tvstep(p01, av0.y, wB.y, vv.y);
            tvstep(p10, av1.y, wA.y, vv.y);
            tvstep(p11, av1.y, wB.y, vv.y);
        }
        __syncthreads();
    }
    float s00 = unpk_sum(p00), s01 = unpk_sum(p01);
    float s10 = unpk_sum(p10), s11 = unpk_sum(p11);
    int ca = c0 + lane, cb = c0 + lane + 32;
    int base0 = (bt0 + warp) * C_;
    int base1 = (bt0 + warp + 8) * C_;
    if (ca < C_) {
        out[base0 + ca] = s00;
        out[base1 + ca] = s10;
    }
    if (cb < C_) {
        out[base0 + cb] = s01;
        out[base1 + cb] = s11;
    }
}

// ---------------- K5: softmax over T per (b,c), coalesced ----------------
__global__ void softmax_kernel() {
    __shared__ float redm[8][33], reds[8][33];
    int cl = threadIdx.x & 31;
    int tg = threadIdx.x >> 5;     // 0..7
    int b  = blockIdx.y;
    int c  = blockIdx.x * 32 + cl;
    bool ok = c < C_;
    int cc = ok ? c : C_ - 1;

    float v[16];
    float m = -1e30f;
#pragma unroll
    for (int i = 0; i < 16; i++) {
        int idx = (b * T_ + tg + i * 8) * C_ + cc;
        v[i] = g_score0[idx] + g_score1[idx];
        m = fmaxf(m, v[i]);
    }
    redm[tg][cl] = m;
    __syncthreads();
    m = redm[0][cl];
#pragma unroll
    for (int g = 1; g < 8; g++) m = fmaxf(m, redm[g][cl]);

    float s = 0.f;
#pragma unroll
    for (int i = 0; i < 16; i++) {
        v[i] = __expf(v[i] - m);
        s += v[i];
    }
    reds[tg][cl] = s;
    __syncthreads();
    s = reds[0][cl];
#pragma unroll
    for (int g = 1; g < 8; g++) s += reds[g][cl];
    float inv = 1.f / s;
    if (ok) {
#pragma unroll
        for (int i = 0; i < 16; i++)
            g_coef[(b * T_ + tg + i * 8) * C_ + c] = v[i] * inv;
    }
}

// ---------------- K6: out[b,c,d] = sum_t coef[b,t,c] * audio[b,t,d] ----------------
// TN, 64c x 128d tile, 128 threads, 8x8 n-paired micro. grid (9, 8, 2).
__global__ void __launch_bounds__(128) pool8(const float* __restrict__ audio,
                                             float* __restrict__ out) {
    __shared__ __align__(16) float As[16 * 64];    // [k=t][c]
    __shared__ __align__(16) float Bs[16 * 128];   // [k=t][d]
    int b = blockIdx.z;
    const float* coefb = g_coef + (size_t)b * T_ * C_;
    const float* audb  = audio + (size_t)b * T_ * DA_;
    float* Cout = out + (size_t)b * C_ * DA_;
    int tid = threadIdx.x;
    int m0 = blockIdx.x * 64;
    int n0 = blockIdx.y * 128;

    int ac = tid & 63;             // c lane
    int atg = tid >> 6;            // 0/1 -> k offset 0/8
    int gmc = min(m0 + ac, C_ - 1);
    int gnd = n0 + tid;            // d column for B loads

    int tx = tid & 15, ty = tid >> 4;

    u64 acc[8][4];
#pragma unroll
    for (int i = 0; i < 8; i++)
#pragma unroll
        for (int j = 0; j < 4; j++) acc[i][j] = 0ull;

    float a8[8], b16[16];
#pragma unroll
    for (int i = 0; i < 8; i++)
        a8[i] = coefb[(size_t)(atg * 8 + i) * C_ + gmc];
#pragma unroll
    for (int i = 0; i < 16; i++)
        b16[i] = audb[(size_t)i * DA_ + gnd];

    for (int k0 = 0; k0 < T_; k0 += 16) {
#pragma unroll
        for (int i = 0; i < 8; i++) As[(atg * 8 + i) * 64 + ac] = a8[i];
#pragma unroll
        for (int i = 0; i < 16; i++) Bs[i * 128 + tid] = b16[i];
        __syncthreads();

        float na8[8], nb16[16];
        int kn = k0 + 16;
        bool more = kn < T_;
        if (more) {
#pragma unroll
            for (int i = 0; i < 8; i++)
                na8[i] = coefb[(size_t)(kn + atg * 8 + i) * C_ + gmc];
#pragma unroll
            for (int i = 0; i < 16; i++)
                nb16[i] = audb[(size_t)(kn + i) * DA_ + gnd];
        }

#pragma unroll
        for (int k = 0; k < 16; k++) {
            float4 amA = *(const float4*)&As[k * 64 + ty * 8];
            float4 amB = *(const float4*)&As[k * 64 + ty * 8 + 4];
            ulonglong2 bn0 = *(const ulonglong2*)&Bs[k * 128 + tx * 8];
            ulonglong2 bn1 = *(const ulonglong2*)&Bs[k * 128 + tx * 8 + 4];
            float am[8] = {amA.x, amA.y, amA.z, amA.w, amB.x, amB.y, amB.z, amB.w};
#pragma unroll
            for (int i = 0; i < 8; i++) {
                u64 p = dup2(am[i]);
                fma2(acc[i][0], p, bn0.x);
                fma2(acc[i][1], p, bn0.y);
                fma2(acc[i][2], p, bn1.x);
                fma2(acc[i][3], p, bn1.y);
            }
        }
        __syncthreads();
        if (more) {
#pragma unroll
            for (int i = 0; i < 8; i++) a8[i] = na8[i];
#pragma unroll
            for (int i = 0; i < 16; i++) b16[i] = nb16[i];
        }
    }

#pragma unroll
    for (int i = 0; i < 8; i++) {
        int gm2 = m0 + ty * 8 + i;
        if (gm2 >= C_) continue;
        ulonglong2 o0, o1;
        o0.x = acc[i][0]; o0.y = acc[i][1];
        o1.x = acc[i][2]; o1.y = acc[i][3];
        *(ulonglong2*)&Cout[(size_t)gm2 * DA_ + n0 + tx * 8] = o0;
        *(ulonglong2*)&Cout[(size_t)gm2 * DA_ + n0 + tx * 8 + 4] = o1;
    }
}

// ---------------- launch ----------------
extern "C" void kernel_launch(void* const* d_in, const int* in_sizes, int n_in,
                              void* d_out, int out_size) {
    const float* audio = (const float*)d_in[0];   // [B,T,DA]
    const float* word  = (const float*)d_in[1];   // [C,DW]
    const float* W1    = (const float*)d_in[2];   // [H,DA]
    const float* W2    = (const float*)d_in[3];   // [H,DW]
    const float* W3    = (const float*)d_in[4];   // [H,H]
    const float* Wa    = (const float*)d_in[6];   // [1,H]
    float* out = (float*)d_out;                   // [B,C,DA]
    (void)in_sizes; (void)n_in; (void)out_size;

    // (1) fused: fc_1 gemm (split-K 4) + fc_2 gemm + veff prep, 64x128 tiles 8x8
    fat_kernel<<<328, 128>>>(audio, word, W1, W2, W3, Wa);
    // (2) fused tanh-dot score, f32x2 packed
    score_kernel<<<dim3(BT_ / 16, (C_ + 63) / 64, 2), 256>>>();
    // (3) softmax over T, coalesced
    softmax_kernel<<<dim3((C_ + 31) / 32, B_), 256>>>();
    // (4) softmax-weighted pooling, 64x128 tiles 8x8 (PROFILED SLOT)
    pool8<<<dim3((C_ + 63) / 64, DA_ / 128, B_), 128>>>(audio, out);
}

// round 10
// speedup vs baseline: 1.0021x; 1.0021x over previous
#include <cuda_runtime.h>
#include <cuda_bf16.h>

// Problem constants
#define B_   2
#define T_   128
#define C_   527
#define DA_  1024
#define DW_  300
#define H_   1024
#define BT_  (B_ * T_)   // 256

typedef unsigned long long u64;

// ---------------- device scratch ----------------
__device__ float g_apart[4 * BT_ * H_];  // split-K-4 partials for fc_1
__device__ float g_w[C_ * H_];           // fc_2 output [527,1024]
__device__ float g_vpart[4 * H_];        // veff partials (4 o-chunks)
__device__ float g_score0[BT_ * C_];     // partial score (h first half)
__device__ float g_score1[BT_ * C_];     // partial score (h second half)
__device__ float g_coef[BT_ * C_];       // softmax over T

__device__ __forceinline__ float tanh_fast(float x) {
    float y;
    asm("tanh.approx.f32 %0, %1;" : "=f"(y) : "f"(x));
    return y;
}
__device__ __forceinline__ void fma2(u64& d, u64 a, u64 b) {
    asm("fma.rn.f32x2 %0, %1, %2, %0;" : "+l"(d) : "l"(a), "l"(b));
}
__device__ __forceinline__ u64 dup2(float a) {
    u64 r;
    asm("mov.b64 %0, {%1, %1};" : "=l"(r) : "f"(a));
    return r;
}
__device__ __forceinline__ float unpk_sum(u64 v) {
    float lo, hi;
    asm("mov.b64 {%0,%1}, %2;" : "=f"(lo), "=f"(hi) : "l"(v));
    return lo + hi;
}
// acc += tanh(a*w) * v, packed over an h-pair
__device__ __forceinline__ void tvstep(u64& acc, u64 a, u64 w, u64 v) {
    u64 x;
    asm("mul.rn.f32x2 %0, %1, %2;" : "=l"(x) : "l"(a), "l"(w));
    float xl, xh;
    asm("mov.b64 {%0,%1}, %2;" : "=f"(xl), "=f"(xh) : "l"(x));
    float tl = tanh_fast(xl), th = tanh_fast(xh);
    u64 t;
    asm("mov.b64 %0, {%1,%2};" : "=l"(t) : "f"(tl), "f"(th));
    asm("fma.rn.f32x2 %0, %1, %2, %0;" : "+l"(acc) : "l"(t), "l"(v));
}

// ---------------- GEMM 8x8 n-paired: C[M,N] = A[M,K] . B[N,K]^T ----------------
// 64x128 tile, 128 threads, 8m x 8n microtile, f32x2 paired over n.
// As: [16 k][64 m] scalar; Bs: [16 k][128 n] scalar. N must be a multiple of 128.
__device__ __forceinline__ void gemm_nt8(const float* __restrict__ A,
                                         const float* __restrict__ B,
                                         float* __restrict__ C,
                                         int M, int N, int K, int Kc,
                                         int bx, int by, int bz,
                                         int tid, float* As, float* Bs) {
    int m0 = bx * 64;
    int n0 = by * 128;
    int k0g = bz * Kc;
    int Kend = min(k0g + Kc, K);
    float* Cout = C + (size_t)bz * M * N;

    int ar = tid >> 1;             // A row 0..63
    int ako = (tid & 1) * 8;       // A k offset 0/8
    int gmA = min(m0 + ar, M - 1);
    const float* Ap = A + (size_t)gmA * K + ako;
    const float* Bp = B + (size_t)(n0 + tid) * K;   // B row = n0+tid, all 16 k

    int tx = tid & 15;             // n = n0 + tx*8
    int ty = tid >> 4;             // m = m0 + ty*8

    u64 acc[8][4];
#pragma unroll
    for (int i = 0; i < 8; i++)
#pragma unroll
        for (int j = 0; j < 4; j++) acc[i][j] = 0ull;

    float a8[8], b16[16];
    {
        int kk = k0g;
        if (kk + 16 <= Kend) {
            float4 t0 = *(const float4*)(Ap + kk);
            float4 t1 = *(const float4*)(Ap + kk + 4);
            a8[0]=t0.x; a8[1]=t0.y; a8[2]=t0.z; a8[3]=t0.w;
            a8[4]=t1.x; a8[5]=t1.y; a8[6]=t1.z; a8[7]=t1.w;
#pragma unroll
            for (int q = 0; q < 4; q++) {
                float4 t = *(const float4*)(Bp + kk + q * 4);
                b16[q*4+0]=t.x; b16[q*4+1]=t.y; b16[q*4+2]=t.z; b16[q*4+3]=t.w;
            }
        } else {
#pragma unroll
            for (int i = 0; i < 8; i++) a8[i] = (kk + ako + i < Kend) ? Ap[kk + i] : 0.f;
#pragma unroll
            for (int i = 0; i < 16; i++) b16[i] = (kk + i < Kend) ? Bp[kk + i] : 0.f;
        }
    }

    for (int k0 = k0g; k0 < Kend; k0 += 16) {
#pragma unroll
        for (int i = 0; i < 8; i++) As[(ako + i) * 64 + ar] = a8[i];
#pragma unroll
        for (int i = 0; i < 16; i++) Bs[i * 128 + tid] = b16[i];
        __syncthreads();

        float na8[8], nb16[16];
        int kn = k0 + 16;
        bool more = kn < Kend;
        if (more) {
            if (kn + 16 <= Kend) {
                float4 t0 = *(const float4*)(Ap + kn);
                float4 t1 = *(const float4*)(Ap + kn + 4);
                na8[0]=t0.x; na8[1]=t0.y; na8[2]=t0.z; na8[3]=t0.w;
                na8[4]=t1.x; na8[5]=t1.y; na8[6]=t1.z; na8[7]=t1.w;
#pragma unroll
                for (int q = 0; q < 4; q++) {
                    float4 t = *(const float4*)(Bp + kn + q * 4);
                    nb16[q*4+0]=t.x; nb16[q*4+1]=t.y; nb16[q*4+2]=t.z; nb16[q*4+3]=t.w;
                }
            } else {
#pragma unroll
                for (int i = 0; i < 8; i++) na8[i] = (kn + ako + i < Kend) ? Ap[kn + i] : 0.f;
#pragma unroll
                for (int i = 0; i < 16; i++) nb16[i] = (kn + i < Kend) ? Bp[kn + i] : 0.f;
            }
        }

#pragma unroll
        for (int k = 0; k < 16; k++) {
            float4 amA = *(const float4*)&As[k * 64 + ty * 8];
            float4 amB = *(const float4*)&As[k * 64 + ty * 8 + 4];
            ulonglong2 bn0 = *(const ulonglong2*)&Bs[k * 128 + tx * 8];
            ulonglong2 bn1 = *(const ulonglong2*)&Bs[k * 128 + tx * 8 + 4];
            float am[8] = {amA.x, amA.y, amA.z, amA.w, amB.x, amB.y, amB.z, amB.w};
#pragma unroll
            for (int i = 0; i < 8; i++) {
                u64 p = dup2(am[i]);
                fma2(acc[i][0], p, bn0.x);
                fma2(acc[i][1], p, bn0.y);
                fma2(acc[i][2], p, bn1.x);
                fma2(acc[i][3], p, bn1.y);
            }
        }
        __syncthreads();
        if (more) {
#pragma unroll
            for (int i = 0; i < 8; i++) a8[i] = na8[i];
#pragma unroll
            for (int i = 0; i < 16; i++) b16[i] = nb16[i];
        }
    }

#pragma unroll
    for (int i = 0; i < 8; i++) {
        int gm = m0 + ty * 8 + i;
        if (gm >= M) continue;
        ulonglong2 o0, o1;
        o0.x = acc[i][0]; o0.y = acc[i][1];
        o1.x = acc[i][2]; o1.y = acc[i][3];
        *(ulonglong2*)&Cout[(size_t)gm * N + n0 + tx * 8] = o0;
        *(ulonglong2*)&Cout[(size_t)gm * N + n0 + tx * 8 + 4] = o1;
    }
}

// ---------------- K1 fat kernel: fc_1 gemm + fc_2 gemm + veff prep ----------------
// blocks [0,128): fc_1 split-K-4; [128,200): fc_2; [200,328): veff partials.
__global__ void __launch_bounds__(128) fat_kernel(const float* __restrict__ audio,
                                                  const float* __restrict__ word,
                                                  const float* __restrict__ W1,
                                                  const float* __restrict__ W2,
                                                  const float* __restrict__ W3,
                                                  const float* __restrict__ Wa) {
    __shared__ __align__(16) float As[16 * 64];
    __shared__ __align__(16) float Bs[16 * 128];
    __shared__ float red[4][33];
    int ib = blockIdx.x;
    int tid = threadIdx.x;
    if (ib < 128) {
        // fc_1: a partials = audio @ W1^T, split-K 4 (Kc = 256); 4 m x 8 n tiles
        int r = ib & 31;
        gemm_nt8(audio, W1, (float*)&g_apart[0], BT_, H_, DA_, DA_ / 4,
                 r & 3, r >> 2, ib >> 5, tid, As, Bs);
    } else if (ib < 200) {
        int j = ib - 128;   // 0..71 -> (x 0..8, y 0..7)
        gemm_nt8(word, W2, (float*)&g_w[0], C_, H_, DW_, DW_,
                 j % 9, j / 9, 0, tid, As, Bs);
    } else {
        // veff partials: p = 0..127; hb = p&31 (32 h), ob = p>>5 (256 o rows)
        int p = ib - 200;
        int hb = p & 31, ob = p >> 5;
        int hl = tid & 31;
        int og = tid >> 5;          // 0..3
        int h = hb * 32 + hl;
        float acc = 0.f;
#pragma unroll 8
        for (int o = ob * 256 + og; o < ob * 256 + 256; o += 4)
            acc += Wa[o] * W3[(size_t)o * H_ + h];
        red[og][hl] = acc;
        __syncthreads();
        if (og == 0)
            g_vpart[ob * H_ + h] = red[0][hl] + red[1][hl] + red[2][hl] + red[3][hl];
    }
}

// ---------------- K4: partial score over one H half, f32x2 packed ----------------
// CTA tile 16 bt x 64 c, 256 threads, 2bt x 2c per thread. grid (16, 9, 2).
__global__ void __launch_bounds__(256, 2) score_kernel() {
    __shared__ __align__(16) float a_s[16][64];
    __shared__ __align__(16) float w_s[64][68];
    __shared__ __align__(16) float v_s[64];
    int tid  = threadIdx.x;
    int lane = tid & 31;
    int warp = tid >> 5;            // 0..7
    int bt0  = blockIdx.x * 16;
    int c0   = blockIdx.y * 64;
    int hb0  = blockIdx.z * (H_ / 2);
    float* out = blockIdx.z ? g_score1 : g_score0;
    u64 p00 = 0ull, p01 = 0ull, p10 = 0ull, p11 = 0ull;

    for (int h0 = hb0; h0 < hb0 + H_ / 2; h0 += 64) {
        // a tile with fused split-K-4 merge
        {
            int r = tid >> 4;              // 0..15
            int c4 = (tid & 15) * 4;       // 0..60
            size_t ai = (size_t)(bt0 + r) * H_ + h0 + c4;
            const size_t S = (size_t)BT_ * H_;
            float4 x = *(const float4*)&g_apart[ai];
            float4 y = *(const float4*)&g_apart[S + ai];
            float4 z = *(const float4*)&g_apart[2 * S + ai];
            float4 w = *(const float4*)&g_apart[3 * S + ai];
            x.x = (x.x + y.x) + (z.x + w.x);
            x.y = (x.y + y.y) + (z.y + w.y);
            x.z = (x.z + y.z) + (z.z + w.z);
            x.w = (x.w + y.w) + (z.w + w.w);
            *(float4*)&a_s[r][c4] = x;
        }
        // v tile: sum the 4 o-chunk partials
        if (tid < 64) {
            int h = h0 + tid;
            v_s[tid] = g_vpart[h] + g_vpart[H_ + h] + g_vpart[2 * H_ + h] + g_vpart[3 * H_ + h];
        }
        // w tile, c-major
        {
            int c = tid >> 2, q = tid & 3;
            int cg = c0 + c;
            bool ok = cg < C_;
            const float4* wrow = (const float4*)(g_w + (size_t)(ok ? cg : C_ - 1) * H_ + h0);
            float4 z = make_float4(0.f, 0.f, 0.f, 0.f);
#pragma unroll
            for (int i = 0; i < 4; i++)
                *(float4*)&w_s[c][q * 16 + i * 4] = ok ? wrow[q * 4 + i] : z;
        }
        __syncthreads();

#pragma unroll
        for (int hh = 0; hh < 16; hh++) {
            ulonglong2 av0 = *(const ulonglong2*)&a_s[warp][hh * 4];
            ulonglong2 av1 = *(const ulonglong2*)&a_s[warp + 8][hh * 4];
            ulonglong2 wA  = *(const ulonglong2*)&w_s[lane][hh * 4];
            ulonglong2 wB  = *(const ulonglong2*)&w_s[lane + 32][hh * 4];
            ulonglong2 vv  = *(const ulonglong2*)&v_s[hh * 4];
            tvstep(p00, av0.x, wA.x, vv.x);
            tvstep(p01, av0.x, wB.x, vv.x);
            tvstep(p10, av1.x, wA.x, vv.x);
            tvstep(p11, av1.x, wB.x, vv.x);
            tvstep(p00, av0.y, wA.y, vv.y);
            tvstep(p01, av0.y, wB.y, vv.y);
            tvstep(p10, av1.y, wA.y, vv.y);
            tvstep(p11, av1.y, wB.y, vv.y);
        }
        __syncthreads();
    }
    float s00 = unpk_sum(p00), s01 = unpk_sum(p01);
    float s10 = unpk_sum(p10), s11 = unpk_sum(p11);
    int ca = c0 + lane, cb = c0 + lane + 32;
    int base0 = (bt0 + warp) * C_;
    int base1 = (bt0 + warp + 8) * C_;
    if (ca < C_) {
        out[base0 + ca] = s00;
        out[base1 + ca] = s10;
    }
    if (cb < C_) {
        out[base0 + cb] = s01;
        out[base1 + cb] = s11;
    }
}

// ---------------- K5: softmax over T per (b,c), coalesced ----------------
__global__ void softmax_kernel() {
    __shared__ float redm[8][33], reds[8][33];
    int cl = threadIdx.x & 31;
    int tg = threadIdx.x >> 5;     // 0..7
    int b  = blockIdx.y;
    int c  = blockIdx.x * 32 + cl;
    bool ok = c < C_;
    int cc = ok ? c : C_ - 1;

    float v[16];
    float m = -1e30f;
#pragma unroll
    for (int i = 0; i < 16; i++) {
        int idx = (b * T_ + tg + i * 8) * C_ + cc;
        v[i] = g_score0[idx] + g_score1[idx];
        m = fmaxf(m, v[i]);
    }
    redm[tg][cl] = m;
    __syncthreads();
    m = redm[0][cl];
#pragma unroll
    for (int g = 1; g < 8; g++) m = fmaxf(m, redm[g][cl]);

    float s = 0.f;
#pragma unroll
    for (int i = 0; i < 16; i++) {
        v[i] = __expf(v[i] - m);
        s += v[i];
    }
    reds[tg][cl] = s;
    __syncthreads();
    s = reds[0][cl];
#pragma unroll
    for (int g = 1; g < 8; g++) s += reds[g][cl];
    float inv = 1.f / s;
    if (ok) {
#pragma unroll
        for (int i = 0; i < 16; i++)
            g_coef[(b * T_ + tg + i * 8) * C_ + c] = v[i] * inv;
    }
}

// ---------------- K6: out[b,c,d] = sum_t coef[b,t,c] * audio[b,t,d] ----------------
// TN, 64c x 128d tile, 128 threads, 8x8 n-paired micro. grid (9, 8, 2).
__global__ void __launch_bounds__(128) pool8(const float* __restrict__ audio,
                                             float* __restrict__ out) {
    __shared__ __align__(16) float As[16 * 64];    // [k=t][c]
    __shared__ __align__(16) float Bs[16 * 128];   // [k=t][d]
    int b = blockIdx.z;
    const float* coefb = g_coef + (size_t)b * T_ * C_;
    const float* audb  = audio + (size_t)b * T_ * DA_;
    float* Cout = out + (size_t)b * C_ * DA_;
    int tid = threadIdx.x;
    int m0 = blockIdx.x * 64;
    int n0 = blockIdx.y * 128;

    int ac = tid & 63;             // c lane
    int atg = tid >> 6;            // 0/1 -> k offset 0/8
    int gmc = min(m0 + ac, C_ - 1);
    int gnd = n0 + tid;            // d column for B loads

    int tx = tid & 15, ty = tid >> 4;

    u64 acc[8][4];
#pragma unroll
    for (int i = 0; i < 8; i++)
#pragma unroll
        for (int j = 0; j < 4; j++) acc[i][j] = 0ull;

    float a8[8], b16[16];
#pragma unroll
    for (int i = 0; i < 8; i++)
        a8[i] = coefb[(size_t)(atg * 8 + i) * C_ + gmc];
#pragma unroll
    for (int i = 0; i < 16; i++)
        b16[i] = audb[(size_t)i * DA_ + gnd];

    for (int k0 = 0; k0 < T_; k0 += 16) {
#pragma unroll
        for (int i = 0; i < 8; i++) As[(atg * 8 + i) * 64 + ac] = a8[i];
#pragma unroll
        for (int i = 0; i < 16; i++) Bs[i * 128 + tid] = b16[i];
        __syncthreads();

        float na8[8], nb16[16];
        int kn = k0 + 16;
        bool more = kn < T_;
        if (more) {
#pragma unroll
            for (int i = 0; i < 8; i++)
                na8[i] = coefb[(size_t)(kn + atg * 8 + i) * C_ + gmc];
#pragma unroll
            for (int i = 0; i < 16; i++)
                nb16[i] = audb[(size_t)(kn + i) * DA_ + gnd];
        }

#pragma unroll
        for (int k = 0; k < 16; k++) {
            float4 amA = *(const float4*)&As[k * 64 + ty * 8];
            float4 amB = *(const float4*)&As[k * 64 + ty * 8 + 4];
            ulonglong2 bn0 = *(const ulonglong2*)&Bs[k * 128 + tx * 8];
            ulonglong2 bn1 = *(const ulonglong2*)&Bs[k * 128 + tx * 8 + 4];
            float am[8] = {amA.x, amA.y, amA.z, amA.w, amB.x, amB.y, amB.z, amB.w};
#pragma unroll
            for (int i = 0; i < 8; i++) {
                u64 p = dup2(am[i]);
                fma2(acc[i][0], p, bn0.x);
                fma2(acc[i][1], p, bn0.y);
                fma2(acc[i][2], p, bn1.x);
                fma2(acc[i][3], p, bn1.y);
            }
        }
        __syncthreads();
        if (more) {
#pragma unroll
            for (int i = 0; i < 8; i++) a8[i] = na8[i];
#pragma unroll
            for (int i = 0; i < 16; i++) b16[i] = nb16[i];
        }
    }

#pragma unroll
    for (int i = 0; i < 8; i++) {
        int gm2 = m0 + ty * 8 + i;
        if (gm2 >= C_) continue;
        ulonglong2 o0, o1;
        o0.x = acc[i][0]; o0.y = acc[i][1];
        o1.x = acc[i][2]; o1.y = acc[i][3];
        *(ulonglong2*)&Cout[(size_t)gm2 * DA_ + n0 + tx * 8] = o0;
        *(ulonglong2*)&Cout[(size_t)gm2 * DA_ + n0 + tx * 8 + 4] = o1;
    }
}

// ---------------- launch ----------------
extern "C" void kernel_launch(void* const* d_in, const int* in_sizes, int n_in,
                              void* d_out, int out_size) {
    const float* audio = (const float*)d_in[0];   // [B,T,DA]
    const float* word  = (const float*)d_in[1];   // [C,DW]
    const float* W1    = (const float*)d_in[2];   // [H,DA]
    const float* W2    = (const float*)d_in[3];   // [H,DW]
    const float* W3    = (const float*)d_in[4];   // [H,H]
    const float* Wa    = (const float*)d_in[6];   // [1,H]
    float* out = (float*)d_out;                   // [B,C,DA]
    (void)in_sizes; (void)n_in; (void)out_size;

    // (1) fused: fc_1 gemm (split-K 4) + fc_2 gemm + veff prep, 64x128 tiles 8x8
    fat_kernel<<<328, 128>>>(audio, word, W1, W2, W3, Wa);
    // (2) fused tanh-dot score, f32x2 packed
    score_kernel<<<dim3(BT_ / 16, (C_ + 63) / 64, 2), 256>>>();
    // (3) softmax over T, coalesced
    softmax_kernel<<<dim3((C_ + 31) / 32, B_), 256>>>();
    // (4) softmax-weighted pooling, 64x128 tiles 8x8 (PROFILED SLOT)
    pool8<<<dim3((C_ + 63) / 64, DA_ / 128, B_), 128>>>(audio, out);
}